// round 2
// baseline (speedup 1.0000x reference)
#include <cuda_runtime.h>
#include <cuda_fp16.h>
#include <cstdint>

// ---------------------------------------------------------------------------
// MultiHeadAttention: B=4, L=2048, D=512, H=8, DK=DV=64
// R2: mask bitpacked to uint8 (read once from DRAM, L2-resident after);
//     P scratch eliminated via 2-pass flash scheme:
//       pass A (rowsum_kernel): S=QK^T, mask, exp -> 1/rowsum only
//       pass B (attn_kernel):   recompute S, normalize, stream attn (.cs),
//                               O = Pn@V fused, epilogue permute into xin
// ---------------------------------------------------------------------------

#define DEV static __device__ __forceinline__

constexpr int Bb = 4, Ll = 2048, Dd = 512, Hh = 8;
constexpr int BL = Bb * Ll;   // 8192
constexpr int BH = Bb * Hh;   // 32
constexpr float INV_TEMP = 0.125f;   // 1/sqrt(64)
constexpr float LN_EPS = 1e-5f;

// ------------------------- scratch (static device mem) ---------------------
__device__ __half g_q16[BL * Dd];
__device__ __half g_k16[BL * Dd];
__device__ __half g_v16[BL * Dd];
__device__ __half g_wq16[Dd * Dd];
__device__ __half g_wv16[Dd * Dd];
__device__ __half g_wf16[Dd * Dd];
__device__ __half g_qh[BL * Dd];     // (B,H,L,64) head layout, pre-scaled 1/TEMP
__device__ __half g_kh[BL * Dd];
__device__ __half g_vh[BL * Dd];
__device__ unsigned char g_mask8[(size_t)Bb * Ll * Ll];  // 16.78 MB
__device__ float  g_invs[BH * Ll];
__device__ __half g_xin[BL * Dd];    // FC input (already permuted), fp16
__device__ float  g_x2[BL * Dd];     // FC output fp32

// ------------------------- mma / ldmatrix helpers ---------------------------
DEV uint32_t sptr(const void* p) { return (uint32_t)__cvta_generic_to_shared(p); }

DEV void ldm_x4(uint32_t r[4], uint32_t addr) {
    asm volatile("ldmatrix.sync.aligned.m8n8.x4.shared.b16 {%0,%1,%2,%3},[%4];"
                 : "=r"(r[0]), "=r"(r[1]), "=r"(r[2]), "=r"(r[3]) : "r"(addr));
}
DEV void ldm_x4_t(uint32_t r[4], uint32_t addr) {
    asm volatile("ldmatrix.sync.aligned.m8n8.x4.trans.shared.b16 {%0,%1,%2,%3},[%4];"
                 : "=r"(r[0]), "=r"(r[1]), "=r"(r[2]), "=r"(r[3]) : "r"(addr));
}
DEV void mma16816(float c[4], const uint32_t a[4], uint32_t b0, uint32_t b1) {
    asm volatile(
        "mma.sync.aligned.m16n8k16.row.col.f32.f16.f16.f32 "
        "{%0,%1,%2,%3},{%4,%5,%6,%7},{%8,%9},{%0,%1,%2,%3};"
        : "+f"(c[0]), "+f"(c[1]), "+f"(c[2]), "+f"(c[3])
        : "r"(a[0]), "r"(a[1]), "r"(a[2]), "r"(a[3]), "r"(b0), "r"(b1));
}

// head layout index for (row r in [0,8192), col c in [0,512))
DEV size_t head_idx(int r, int c) {
    int b = r >> 11, l = r & 2047, h = c >> 6, d = c & 63;
    return ((size_t)((b << 3) | h) * 2048 + l) * 64 + d;
}

// ------------------------- small utility kernels ----------------------------
__global__ void f2h_kernel(const float* __restrict__ in, __half* __restrict__ out, int n) {
    int i = (blockIdx.x * blockDim.x + threadIdx.x) * 4;
    if (i < n) {
        float4 v = *(const float4*)(in + i);
        *(__half2*)(out + i)     = __floats2half2_rn(v.x, v.y);
        *(__half2*)(out + i + 2) = __floats2half2_rn(v.z, v.w);
    }
}

__global__ void mask8_kernel(const int* __restrict__ in, unsigned char* __restrict__ out, int n) {
    int i = (blockIdx.x * blockDim.x + threadIdx.x) * 4;
    if (i < n) {
        int4 m = *(const int4*)(in + i);
        uchar4 o;
        o.x = (unsigned char)m.x; o.y = (unsigned char)m.y;
        o.z = (unsigned char)m.z; o.w = (unsigned char)m.w;
        *(uchar4*)(out + i) = o;
    }
}

// ------------------------- generic GEMM: C = A(M,K) @ W(N,K)^T --------------
// EPI 0: out = half, head layout, (acc+bias)*scale
// EPI 1: out = float, row-major,  acc+bias
template <int EPI>
__global__ __launch_bounds__(256)
void gemm_kernel(const __half* __restrict__ A, const __half* __restrict__ W,
                 const float* __restrict__ bias, void* __restrict__ out,
                 int K, int N, float scale)
{
    constexpr int BM = 128, BN = 128, BK = 32;
    constexpr int AS = 40, BS = 40;
    __shared__ __half As[BM * AS];
    __shared__ __half Bs[BN * BS];

    int tid = threadIdx.x;
    int warp = tid >> 5, lane = tid & 31;
    int wm = warp >> 1, wn = warp & 1;
    int m0 = blockIdx.y * BM, n0 = blockIdx.x * BN;

    float c[2][8][4];
#pragma unroll
    for (int i = 0; i < 2; i++)
#pragma unroll
        for (int j = 0; j < 8; j++)
#pragma unroll
            for (int k = 0; k < 4; k++) c[i][j][k] = 0.0f;

    for (int k0 = 0; k0 < K; k0 += BK) {
#pragma unroll
        for (int i = 0; i < 2; i++) {
            int u = tid + i * 256;
            int r = u >> 2, s = u & 3;
            *(int4*)&As[r * AS + s * 8] = *(const int4*)&A[(size_t)(m0 + r) * K + k0 + s * 8];
            *(int4*)&Bs[r * BS + s * 8] = *(const int4*)&W[(size_t)(n0 + r) * K + k0 + s * 8];
        }
        __syncthreads();
#pragma unroll
        for (int ks = 0; ks < 2; ks++) {
            uint32_t a[2][4];
#pragma unroll
            for (int mi = 0; mi < 2; mi++) {
                int row = wm * 32 + mi * 16 + (lane & 15);
                int col = ks * 16 + ((lane >> 4) << 3);
                ldm_x4(a[mi], sptr(&As[row * AS + col]));
            }
            uint32_t bb[4][4];
#pragma unroll
            for (int p = 0; p < 4; p++) {
                int tg = lane >> 3, idx = lane & 7;
                int row = wn * 64 + p * 16 + ((tg >> 1) << 3) + idx;
                int col = ks * 16 + ((tg & 1) << 3);
                ldm_x4(bb[p], sptr(&Bs[row * BS + col]));
            }
#pragma unroll
            for (int mi = 0; mi < 2; mi++)
#pragma unroll
                for (int p = 0; p < 4; p++) {
                    mma16816(c[mi][2 * p],     a[mi], bb[p][0], bb[p][1]);
                    mma16816(c[mi][2 * p + 1], a[mi], bb[p][2], bb[p][3]);
                }
        }
        __syncthreads();
    }

    int grp = lane >> 2, tig = lane & 3;
#pragma unroll
    for (int mi = 0; mi < 2; mi++)
#pragma unroll
        for (int ni = 0; ni < 8; ni++) {
            int rr = m0 + wm * 32 + mi * 16 + grp;
            int cC = n0 + wn * 64 + ni * 8 + tig * 2;
            float b0 = bias[cC], b1 = bias[cC + 1];
#pragma unroll
            for (int ro = 0; ro < 2; ro++) {
                int r2 = rr + ro * 8;
                float v0 = c[mi][ni][ro * 2 + 0] + b0;
                float v1 = c[mi][ni][ro * 2 + 1] + b1;
                if (EPI == 0) {
                    v0 *= scale; v1 *= scale;
                    *(__half2*)&((__half*)out)[head_idx(r2, cC)] = __floats2half2_rn(v0, v1);
                } else {
                    *(float2*)&((float*)out)[(size_t)r2 * N + cC] = make_float2(v0, v1);
                }
            }
        }
}

// ------------------------- pass A: row sums ---------------------------------
// per block: q-tile of 128 rows for one (b,h); loops over all 2048 k in tiles
// of 64. Q fragments in registers; K tile in 18KB shared buffer.
__global__ __launch_bounds__(256)
void rowsum_kernel(const __half* __restrict__ qh, const __half* __restrict__ kh,
                   const unsigned char* __restrict__ mask8, float* __restrict__ invs)
{
    __shared__ __half SB[128 * 72];
    __shared__ float rs[128];
    int bh = blockIdx.y;
    int m0 = blockIdx.x * 128;
    const __half* Q = qh + (size_t)bh * Ll * 64;
    const __half* K = kh + (size_t)bh * Ll * 64;
    int b = bh >> 3;
    int tid = threadIdx.x, warp = tid >> 5, lane = tid & 31;
    int wm = warp >> 1, wn = warp & 1;
    int grp = lane >> 2, tig = lane & 3;
    int tg = lane >> 3, idx = lane & 7;

    // load Q tile into SB, then into register fragments
#pragma unroll
    for (int i = 0; i < 4; i++) {
        int u = tid + i * 256; int r = u >> 3, s = u & 7;
        *(int4*)&SB[r * 72 + s * 8] = *(const int4*)&Q[(size_t)(m0 + r) * 64 + s * 8];
    }
    if (tid < 128) rs[tid] = 0.0f;
    __syncthreads();
    uint32_t qf[4][2][4];
#pragma unroll
    for (int ks = 0; ks < 4; ks++)
#pragma unroll
        for (int mi = 0; mi < 2; mi++) {
            int row = wm * 32 + mi * 16 + (lane & 15);
            int col = ks * 16 + ((lane >> 4) << 3);
            ldm_x4(qf[ks][mi], sptr(&SB[row * 72 + col]));
        }

    float rsum[2][2] = {{0.0f, 0.0f}, {0.0f, 0.0f}};

    for (int k0 = 0; k0 < Ll; k0 += 64) {
        __syncthreads();
#pragma unroll
        for (int i = 0; i < 2; i++) {
            int u = tid + i * 256; int r = u >> 3, s = u & 7;
            *(int4*)&SB[r * 72 + s * 8] = *(const int4*)&K[(size_t)(k0 + r) * 64 + s * 8];
        }
        __syncthreads();
        float c[2][4][4];
#pragma unroll
        for (int i = 0; i < 2; i++)
#pragma unroll
            for (int j = 0; j < 4; j++)
#pragma unroll
                for (int k = 0; k < 4; k++) c[i][j][k] = 0.0f;
#pragma unroll
        for (int ks = 0; ks < 4; ks++) {
            uint32_t bb[2][4];
#pragma unroll
            for (int p = 0; p < 2; p++) {
                int row = wn * 32 + p * 16 + ((tg >> 1) << 3) + idx;
                int col = ks * 16 + ((tg & 1) << 3);
                ldm_x4(bb[p], sptr(&SB[row * 72 + col]));
            }
#pragma unroll
            for (int mi = 0; mi < 2; mi++)
#pragma unroll
                for (int p = 0; p < 2; p++) {
                    mma16816(c[mi][2 * p],     qf[ks][mi], bb[p][0], bb[p][1]);
                    mma16816(c[mi][2 * p + 1], qf[ks][mi], bb[p][2], bb[p][3]);
                }
        }
#pragma unroll
        for (int mi = 0; mi < 2; mi++)
#pragma unroll
            for (int ro = 0; ro < 2; ro++) {
                int q = m0 + wm * 32 + mi * 16 + ro * 8 + grp;
                size_t mrow = ((size_t)b * Ll + q) * Ll + k0;
                float acc = 0.0f;
#pragma unroll
                for (int ni = 0; ni < 4; ni++) {
                    int kk = wn * 32 + ni * 8 + tig * 2;
                    uchar2 mm = *(const uchar2*)&mask8[mrow + kk];
                    float p0 = mm.x ? 0.0f : __expf(c[mi][ni][ro * 2 + 0]);
                    float p1 = mm.y ? 0.0f : __expf(c[mi][ni][ro * 2 + 1]);
                    acc += p0 + p1;
                }
                rsum[mi][ro] += acc;
            }
    }
#pragma unroll
    for (int mi = 0; mi < 2; mi++)
#pragma unroll
        for (int ro = 0; ro < 2; ro++) {
            float s = rsum[mi][ro];
            s += __shfl_xor_sync(0xffffffffu, s, 1);
            s += __shfl_xor_sync(0xffffffffu, s, 2);
            if (tig == 0) atomicAdd(&rs[wm * 32 + mi * 16 + ro * 8 + grp], s);
        }
    __syncthreads();
    if (tid < 128) invs[bh * Ll + m0 + tid] = 1.0f / rs[tid];
}

// ------------------------- pass B: attn out + O @ permute -------------------
__global__ __launch_bounds__(256)
void attn_kernel(const __half* __restrict__ qh, const __half* __restrict__ kh,
                 const __half* __restrict__ vh, const unsigned char* __restrict__ mask8,
                 const float* __restrict__ invs, float* __restrict__ attn_out,
                 __half* __restrict__ xin)
{
    __shared__ __half Ks[64 * 72];
    __shared__ __half Vs[64 * 72];
    __shared__ __half Ps[128 * 72];
    int bh = blockIdx.y;
    int m0 = blockIdx.x * 128;
    const __half* Q = qh + (size_t)bh * Ll * 64;
    const __half* K = kh + (size_t)bh * Ll * 64;
    const __half* V = vh + (size_t)bh * Ll * 64;
    float* aout = attn_out + (size_t)bh * Ll * Ll;
    int b = bh >> 3;
    int tid = threadIdx.x, warp = tid >> 5, lane = tid & 31;
    int wm = warp >> 1, wn = warp & 1;
    int grp = lane >> 2, tig = lane & 3;
    int tg = lane >> 3, idx = lane & 7;

    // Q tile -> Ps buffer -> register fragments
#pragma unroll
    for (int i = 0; i < 4; i++) {
        int u = tid + i * 256; int r = u >> 3, s = u & 7;
        *(int4*)&Ps[r * 72 + s * 8] = *(const int4*)&Q[(size_t)(m0 + r) * 64 + s * 8];
    }
    __syncthreads();
    uint32_t qf[4][2][4];
#pragma unroll
    for (int ks = 0; ks < 4; ks++)
#pragma unroll
        for (int mi = 0; mi < 2; mi++) {
            int row = wm * 32 + mi * 16 + (lane & 15);
            int col = ks * 16 + ((lane >> 4) << 3);
            ldm_x4(qf[ks][mi], sptr(&Ps[row * 72 + col]));
        }
    float invr[2][2];
#pragma unroll
    for (int mi = 0; mi < 2; mi++)
#pragma unroll
        for (int ro = 0; ro < 2; ro++)
            invr[mi][ro] = invs[bh * Ll + m0 + wm * 32 + mi * 16 + ro * 8 + grp];

    float o[2][4][4];
#pragma unroll
    for (int i = 0; i < 2; i++)
#pragma unroll
        for (int j = 0; j < 4; j++)
#pragma unroll
            for (int k = 0; k < 4; k++) o[i][j][k] = 0.0f;

    for (int k0 = 0; k0 < Ll; k0 += 64) {
        __syncthreads();   // prev PV (reads Ps/Vs) done; also guards qf ldmatrix on iter 0
#pragma unroll
        for (int i = 0; i < 2; i++) {
            int u = tid + i * 256; int r = u >> 3, s = u & 7;
            *(int4*)&Ks[r * 72 + s * 8] = *(const int4*)&K[(size_t)(k0 + r) * 64 + s * 8];
            *(int4*)&Vs[r * 72 + s * 8] = *(const int4*)&V[(size_t)(k0 + r) * 64 + s * 8];
        }
        __syncthreads();

        // S = Q @ K^T  (128 x 64)
        float c[2][4][4];
#pragma unroll
        for (int i = 0; i < 2; i++)
#pragma unroll
            for (int j = 0; j < 4; j++)
#pragma unroll
                for (int k = 0; k < 4; k++) c[i][j][k] = 0.0f;
#pragma unroll
        for (int ks = 0; ks < 4; ks++) {
            uint32_t bb[2][4];
#pragma unroll
            for (int p = 0; p < 2; p++) {
                int row = wn * 32 + p * 16 + ((tg >> 1) << 3) + idx;
                int col = ks * 16 + ((tg & 1) << 3);
                ldm_x4(bb[p], sptr(&Ks[row * 72 + col]));
            }
#pragma unroll
            for (int mi = 0; mi < 2; mi++)
#pragma unroll
                for (int p = 0; p < 2; p++) {
                    mma16816(c[mi][2 * p],     qf[ks][mi], bb[p][0], bb[p][1]);
                    mma16816(c[mi][2 * p + 1], qf[ks][mi], bb[p][2], bb[p][3]);
                }
        }

        // mask + exp + normalize; stream attn (fp32, .cs) ; stash Pn fp16 in smem
#pragma unroll
        for (int mi = 0; mi < 2; mi++)
#pragma unroll
            for (int ro = 0; ro < 2; ro++) {
                int ql = wm * 32 + mi * 16 + ro * 8 + grp;
                int q = m0 + ql;
                size_t mrow = ((size_t)b * Ll + q) * Ll + k0;
                size_t arow = (size_t)q * Ll + k0;
                float inv = invr[mi][ro];
#pragma unroll
                for (int ni = 0; ni < 4; ni++) {
                    int kk = wn * 32 + ni * 8 + tig * 2;
                    uchar2 mm = *(const uchar2*)&mask8[mrow + kk];
                    float p0 = mm.x ? 0.0f : __expf(c[mi][ni][ro * 2 + 0]) * inv;
                    float p1 = mm.y ? 0.0f : __expf(c[mi][ni][ro * 2 + 1]) * inv;
                    __stcs((float2*)&aout[arow + kk], make_float2(p0, p1));
                    *(__half2*)&Ps[ql * 72 + kk] = __floats2half2_rn(p0, p1);
                }
            }
        __syncthreads();

        // O += Pn @ V  (128 x 64)
#pragma unroll
        for (int ks2 = 0; ks2 < 4; ks2++) {
            uint32_t a[2][4], bb[2][4];
#pragma unroll
            for (int mi = 0; mi < 2; mi++) {
                int row = wm * 32 + mi * 16 + (lane & 15);
                int col = ks2 * 16 + ((lane >> 4) << 3);
                ldm_x4(a[mi], sptr(&Ps[row * 72 + col]));
            }
#pragma unroll
            for (int p = 0; p < 2; p++) {
                int krow = ks2 * 16 + ((tg & 1) << 3) + idx;
                int col = wn * 32 + p * 16 + ((tg >> 1) << 3);
                ldm_x4_t(bb[p], sptr(&Vs[krow * 72 + col]));
            }
#pragma unroll
            for (int mi = 0; mi < 2; mi++)
#pragma unroll
                for (int p = 0; p < 2; p++) {
                    mma16816(o[mi][2 * p],     a[mi], bb[p][0], bb[p][1]);
                    mma16816(o[mi][2 * p + 1], a[mi], bb[p][2], bb[p][3]);
                }
        }
    }

    // epilogue: write xin with the reference's buffer-reinterpretation index
    int hp = bh >> 2, bp = bh & 3;
#pragma unroll
    for (int mi = 0; mi < 2; mi++)
#pragma unroll
        for (int ni = 0; ni < 4; ni++) {
            int rr = m0 + wm * 32 + mi * 16 + grp;
            int cC = wn * 32 + ni * 8 + tig * 2;
#pragma unroll
            for (int ro = 0; ro < 2; ro++) {
                int l = rr + ro * 8;
                size_t n = (size_t)hp * 8192 + (size_t)l * 4 + bp;
                *(__half2*)&xin[n * 64 + cC] =
                    __floats2half2_rn(o[mi][ni][ro * 2], o[mi][ni][ro * 2 + 1]);
            }
        }
}

// ------------------------- layernorm (+ residual) ---------------------------
__global__ __launch_bounds__(128)
void ln_kernel(const float* __restrict__ x2, const float* __restrict__ resid,
               const float* __restrict__ g, const float* __restrict__ bta,
               float* __restrict__ y)
{
    int r = blockIdx.x;
    const float* xr = x2 + (size_t)r * Dd;
    const float* qr = resid + (size_t)r * Dd;
    int t = threadIdx.x;
    float v[4];
    float s = 0.0f, s2 = 0.0f;
#pragma unroll
    for (int i = 0; i < 4; i++) {
        int cI = t + i * 128;
        v[i] = xr[cI] + qr[cI];
        s += v[i]; s2 += v[i] * v[i];
    }
#pragma unroll
    for (int off = 16; off > 0; off >>= 1) {
        s  += __shfl_xor_sync(0xffffffffu, s,  off);
        s2 += __shfl_xor_sync(0xffffffffu, s2, off);
    }
    __shared__ float ss[4], ss2[4];
    int w = t >> 5, lane = t & 31;
    if (lane == 0) { ss[w] = s; ss2[w] = s2; }
    __syncthreads();
    float S = ss[0] + ss[1] + ss[2] + ss[3];
    float S2 = ss2[0] + ss2[1] + ss2[2] + ss2[3];
    float mu = S / Dd;
    float var = S2 / Dd - mu * mu;
    float rstd = rsqrtf(var + LN_EPS);
#pragma unroll
    for (int i = 0; i < 4; i++) {
        int cI = t + i * 128;
        y[(size_t)r * Dd + cI] = (v[i] - mu) * rstd * g[cI] + bta[cI];
    }
}

// ------------------------- host launcher ------------------------------------
extern "C" void kernel_launch(void* const* d_in, const int* in_sizes, int n_in,
                              void* d_out, int out_size)
{
    (void)in_sizes; (void)n_in; (void)out_size;
    const float* q    = (const float*)d_in[0];
    const float* k    = (const float*)d_in[1];
    const float* v    = (const float*)d_in[2];
    const int*   mask = (const int*)d_in[3];
    const float* wq_w = (const float*)d_in[4];
    const float* wq_b = (const float*)d_in[5];
    const float* wv_w = (const float*)d_in[6];
    const float* wv_b = (const float*)d_in[7];
    const float* fc_w = (const float*)d_in[8];
    const float* fc_b = (const float*)d_in[9];
    const float* ln_g = (const float*)d_in[10];
    const float* ln_b = (const float*)d_in[11];

    float* y_out    = (float*)d_out;
    float* attn_out = y_out + (size_t)BL * Dd;

    __half *q16, *k16, *v16, *wq16, *wv16, *wf16, *qh, *kh, *vh, *xin;
    unsigned char* mask8;
    float *invs, *x2;
    cudaGetSymbolAddress((void**)&q16,  g_q16);
    cudaGetSymbolAddress((void**)&k16,  g_k16);
    cudaGetSymbolAddress((void**)&v16,  g_v16);
    cudaGetSymbolAddress((void**)&wq16, g_wq16);
    cudaGetSymbolAddress((void**)&wv16, g_wv16);
    cudaGetSymbolAddress((void**)&wf16, g_wf16);
    cudaGetSymbolAddress((void**)&qh,   g_qh);
    cudaGetSymbolAddress((void**)&kh,   g_kh);
    cudaGetSymbolAddress((void**)&vh,   g_vh);
    cudaGetSymbolAddress((void**)&mask8, g_mask8);
    cudaGetSymbolAddress((void**)&invs, g_invs);
    cudaGetSymbolAddress((void**)&xin,  g_xin);
    cudaGetSymbolAddress((void**)&x2,   g_x2);

    const int nBig = BL * Dd;          // 4194304
    const int nW   = Dd * Dd;          // 262144
    const int nM   = Bb * Ll * Ll;     // 16777216
    f2h_kernel<<<nBig / 4 / 256, 256>>>(q, q16, nBig);
    f2h_kernel<<<nBig / 4 / 256, 256>>>(k, k16, nBig);
    f2h_kernel<<<nBig / 4 / 256, 256>>>(v, v16, nBig);
    f2h_kernel<<<nW / 4 / 256, 256>>>(wq_w, wq16, nW);
    f2h_kernel<<<nW / 4 / 256, 256>>>(wv_w, wv16, nW);
    f2h_kernel<<<nW / 4 / 256, 256>>>(fc_w, wf16, nW);
    mask8_kernel<<<nM / 4 / 256, 256>>>(mask, mask8, nM);

    dim3 gP(Dd / 128, BL / 128);  // (4, 64)
    gemm_kernel<0><<<gP, 256>>>(q16, wq16, wq_b, qh, Dd, Dd, INV_TEMP);
    gemm_kernel<0><<<gP, 256>>>(k16, wq16, wq_b, kh, Dd, Dd, 1.0f);   // k uses wq (bug preserved)
    gemm_kernel<0><<<gP, 256>>>(v16, wv16, wv_b, vh, Dd, Dd, 1.0f);

    rowsum_kernel<<<dim3(16, 32), 256>>>(qh, kh, mask8, invs);
    attn_kernel<<<dim3(16, 32), 256>>>(qh, kh, vh, mask8, invs, attn_out, xin);

    gemm_kernel<1><<<gP, 256>>>(xin, wf16, fc_b, x2, Dd, Dd, 1.0f);
    ln_kernel<<<BL, 128>>>(x2, q, ln_g, ln_b, y_out);
}

// round 4
// speedup vs baseline: 1.2702x; 1.2702x over previous
#include <cuda_runtime.h>
#include <cuda_fp16.h>
#include <cstdint>

// ---------------------------------------------------------------------------
// MultiHeadAttention: B=4, L=2048, D=512, H=8, DK=DV=64
// R4 = R3 with the pv attn-store epilogue indexing bug fixed.
//   scores: single-shot (K=64, no k-loop), smem-staged coalesced P stores
//   pv:     cp.async double-buffered; O accumulated on UNNORMALIZED P
//           (scale by 1/rowsum at the end); attn store is a decoupled
//           coalesced float4 streaming epilogue
// ---------------------------------------------------------------------------

#define DEV static __device__ __forceinline__

constexpr int Bb = 4, Ll = 2048, Dd = 512, Hh = 8;
constexpr int BL = Bb * Ll;   // 8192
constexpr int BH = Bb * Hh;   // 32
constexpr float INV_TEMP = 0.125f;   // 1/sqrt(64)
constexpr float LN_EPS = 1e-5f;

// ------------------------- scratch (static device mem) ---------------------
__device__ __half g_q16[BL * Dd];
__device__ __half g_k16[BL * Dd];
__device__ __half g_v16[BL * Dd];
__device__ __half g_wq16[Dd * Dd];
__device__ __half g_wv16[Dd * Dd];
__device__ __half g_wf16[Dd * Dd];
__device__ __half g_qh[BL * Dd];     // (B,H,L,64) head layout, pre-scaled 1/TEMP
__device__ __half g_kh[BL * Dd];
__device__ __half g_vh[BL * Dd];
__device__ unsigned char g_mask8[(size_t)Bb * Ll * Ll];  // 16.78 MB
__device__ __half g_p[(size_t)BH * Ll * Ll];   // unnormalized exp scores fp16
__device__ float  g_rowsum[BH * Ll];
__device__ __half g_xin[BL * Dd];    // FC input (already permuted), fp16
__device__ float  g_x2[BL * Dd];     // FC output fp32

// ------------------------- mma / ldmatrix / cp.async helpers ----------------
DEV uint32_t sptr(const void* p) { return (uint32_t)__cvta_generic_to_shared(p); }

DEV void ldm_x4(uint32_t r[4], uint32_t addr) {
    asm volatile("ldmatrix.sync.aligned.m8n8.x4.shared.b16 {%0,%1,%2,%3},[%4];"
                 : "=r"(r[0]), "=r"(r[1]), "=r"(r[2]), "=r"(r[3]) : "r"(addr));
}
DEV void ldm_x4_t(uint32_t r[4], uint32_t addr) {
    asm volatile("ldmatrix.sync.aligned.m8n8.x4.trans.shared.b16 {%0,%1,%2,%3},[%4];"
                 : "=r"(r[0]), "=r"(r[1]), "=r"(r[2]), "=r"(r[3]) : "r"(addr));
}
DEV void mma16816(float c[4], const uint32_t a[4], uint32_t b0, uint32_t b1) {
    asm volatile(
        "mma.sync.aligned.m16n8k16.row.col.f32.f16.f16.f32 "
        "{%0,%1,%2,%3},{%4,%5,%6,%7},{%8,%9},{%0,%1,%2,%3};"
        : "+f"(c[0]), "+f"(c[1]), "+f"(c[2]), "+f"(c[3])
        : "r"(a[0]), "r"(a[1]), "r"(a[2]), "r"(a[3]), "r"(b0), "r"(b1));
}
DEV void cpa16(void* dst_smem, const void* src) {
    asm volatile("cp.async.cg.shared.global [%0],[%1],16;"
                 :: "r"(sptr(dst_smem)), "l"(src));
}
DEV void cpa_commit() { asm volatile("cp.async.commit_group;"); }
template <int N> DEV void cpa_wait() { asm volatile("cp.async.wait_group %0;" :: "n"(N)); }

// head layout index for (row r in [0,8192), col c in [0,512))
DEV size_t head_idx(int r, int c) {
    int b = r >> 11, l = r & 2047, h = c >> 6, d = c & 63;
    return ((size_t)((b << 3) | h) * 2048 + l) * 64 + d;
}

// ------------------------- small utility kernels ----------------------------
__global__ void f2h_kernel(const float* __restrict__ in, __half* __restrict__ out, int n) {
    int i = (blockIdx.x * blockDim.x + threadIdx.x) * 4;
    if (i < n) {
        float4 v = *(const float4*)(in + i);
        *(__half2*)(out + i)     = __floats2half2_rn(v.x, v.y);
        *(__half2*)(out + i + 2) = __floats2half2_rn(v.z, v.w);
    }
}
__global__ void mask8_kernel(const int* __restrict__ in, unsigned char* __restrict__ out, int n) {
    int i = (blockIdx.x * blockDim.x + threadIdx.x) * 4;
    if (i < n) {
        int4 m = *(const int4*)(in + i);
        uchar4 o;
        o.x = (unsigned char)m.x; o.y = (unsigned char)m.y;
        o.z = (unsigned char)m.z; o.w = (unsigned char)m.w;
        *(uchar4*)(out + i) = o;
    }
}
__global__ void zero_kernel(float* p, int n) {
    int i = blockIdx.x * blockDim.x + threadIdx.x;
    if (i < n) p[i] = 0.0f;
}
__global__ void invert_kernel(float* p, int n) {
    int i = blockIdx.x * blockDim.x + threadIdx.x;
    if (i < n) p[i] = 1.0f / p[i];
}

// ------------------------- generic GEMM: C = A(M,K) @ W(N,K)^T --------------
template <int EPI>
__global__ __launch_bounds__(256)
void gemm_kernel(const __half* __restrict__ A, const __half* __restrict__ W,
                 const float* __restrict__ bias, void* __restrict__ out,
                 int K, int N, float scale)
{
    constexpr int BM = 128, BN = 128, BK = 32;
    constexpr int AS = 40, BS = 40;
    __shared__ __half As[BM * AS];
    __shared__ __half Bs[BN * BS];

    int tid = threadIdx.x;
    int warp = tid >> 5, lane = tid & 31;
    int wm = warp >> 1, wn = warp & 1;
    int m0 = blockIdx.y * BM, n0 = blockIdx.x * BN;

    float c[2][8][4];
#pragma unroll
    for (int i = 0; i < 2; i++)
#pragma unroll
        for (int j = 0; j < 8; j++)
#pragma unroll
            for (int k = 0; k < 4; k++) c[i][j][k] = 0.0f;

    for (int k0 = 0; k0 < K; k0 += BK) {
#pragma unroll
        for (int i = 0; i < 2; i++) {
            int u = tid + i * 256;
            int r = u >> 2, s = u & 3;
            *(int4*)&As[r * AS + s * 8] = *(const int4*)&A[(size_t)(m0 + r) * K + k0 + s * 8];
            *(int4*)&Bs[r * BS + s * 8] = *(const int4*)&W[(size_t)(n0 + r) * K + k0 + s * 8];
        }
        __syncthreads();
#pragma unroll
        for (int ks = 0; ks < 2; ks++) {
            uint32_t a[2][4];
#pragma unroll
            for (int mi = 0; mi < 2; mi++) {
                int row = wm * 32 + mi * 16 + (lane & 15);
                int col = ks * 16 + ((lane >> 4) << 3);
                ldm_x4(a[mi], sptr(&As[row * AS + col]));
            }
            uint32_t bb[4][4];
#pragma unroll
            for (int p = 0; p < 4; p++) {
                int tg = lane >> 3, idx = lane & 7;
                int row = wn * 64 + p * 16 + ((tg >> 1) << 3) + idx;
                int col = ks * 16 + ((tg & 1) << 3);
                ldm_x4(bb[p], sptr(&Bs[row * BS + col]));
            }
#pragma unroll
            for (int mi = 0; mi < 2; mi++)
#pragma unroll
                for (int p = 0; p < 4; p++) {
                    mma16816(c[mi][2 * p],     a[mi], bb[p][0], bb[p][1]);
                    mma16816(c[mi][2 * p + 1], a[mi], bb[p][2], bb[p][3]);
                }
        }
        __syncthreads();
    }

    int grp = lane >> 2, tig = lane & 3;
#pragma unroll
    for (int mi = 0; mi < 2; mi++)
#pragma unroll
        for (int ni = 0; ni < 8; ni++) {
            int rr = m0 + wm * 32 + mi * 16 + grp;
            int cC = n0 + wn * 64 + ni * 8 + tig * 2;
            float b0 = bias[cC], b1 = bias[cC + 1];
#pragma unroll
            for (int ro = 0; ro < 2; ro++) {
                int r2 = rr + ro * 8;
                float v0 = c[mi][ni][ro * 2 + 0] + b0;
                float v1 = c[mi][ni][ro * 2 + 1] + b1;
                if (EPI == 0) {
                    v0 *= scale; v1 *= scale;
                    *(__half2*)&((__half*)out)[head_idx(r2, cC)] = __floats2half2_rn(v0, v1);
                } else {
                    *(float2*)&((float*)out)[(size_t)r2 * N + cC] = make_float2(v0, v1);
                }
            }
        }
}

// ------------------------- scores: one-shot QK^T + exp + P ------------------
// grid (16 ktile, 16 qtile, 32 bh); tile 128x128, K=64 (no k-loop).
__global__ __launch_bounds__(256)
void scores_kernel(const __half* __restrict__ qh, const __half* __restrict__ kh,
                   const unsigned char* __restrict__ mask8, __half* __restrict__ P,
                   float* __restrict__ rowsum)
{
    __shared__ __half SM[2 * 128 * 72];          // As | Bs, reused for staging
    __half* As = SM;
    __half* Bs = SM + 128 * 72;

    int bh = blockIdx.z;
    int n0 = blockIdx.x * 128;    // k-tile
    int m0 = blockIdx.y * 128;    // q-tile
    const __half* Q = qh + (size_t)bh * Ll * 64;
    const __half* K = kh + (size_t)bh * Ll * 64;
    int b = bh >> 3;

    int tid = threadIdx.x, warp = tid >> 5, lane = tid & 31;
    int wm = warp >> 1, wn = warp & 1;
    int grp = lane >> 2, tig = lane & 3;
    int tg = lane >> 3, idx = lane & 7;

#pragma unroll
    for (int i = 0; i < 4; i++) {
        int u = tid + i * 256; int r = u >> 3, s = u & 7;
        *(int4*)&As[r * 72 + s * 8] = *(const int4*)&Q[(size_t)(m0 + r) * 64 + s * 8];
        *(int4*)&Bs[r * 72 + s * 8] = *(const int4*)&K[(size_t)(n0 + r) * 64 + s * 8];
    }
    __syncthreads();

    float c[2][8][4];
#pragma unroll
    for (int i = 0; i < 2; i++)
#pragma unroll
        for (int j = 0; j < 8; j++)
#pragma unroll
            for (int k = 0; k < 4; k++) c[i][j][k] = 0.0f;

#pragma unroll
    for (int ks = 0; ks < 4; ks++) {
        uint32_t a[2][4];
#pragma unroll
        for (int mi = 0; mi < 2; mi++) {
            int row = wm * 32 + mi * 16 + (lane & 15);
            int col = ks * 16 + ((lane >> 4) << 3);
            ldm_x4(a[mi], sptr(&As[row * 72 + col]));
        }
        uint32_t bb[4][4];
#pragma unroll
        for (int p = 0; p < 4; p++) {
            int row = wn * 64 + p * 16 + ((tg >> 1) << 3) + idx;
            int col = ks * 16 + ((tg & 1) << 3);
            ldm_x4(bb[p], sptr(&Bs[row * 72 + col]));
        }
#pragma unroll
        for (int mi = 0; mi < 2; mi++)
#pragma unroll
            for (int p = 0; p < 4; p++) {
                mma16816(c[mi][2 * p],     a[mi], bb[p][0], bb[p][1]);
                mma16816(c[mi][2 * p + 1], a[mi], bb[p][2], bb[p][3]);
            }
    }
    __syncthreads();   // As/Bs consumed; reuse SM for staging (stride 136)

    // exp + mask -> stage into SM (row-major 128x128, stride 136) + rowsum
#pragma unroll
    for (int mi = 0; mi < 2; mi++)
#pragma unroll
        for (int ro = 0; ro < 2; ro++) {
            int ql = wm * 32 + mi * 16 + ro * 8 + grp;
            int q = m0 + ql;
            size_t mrow = ((size_t)b * Ll + q) * Ll + n0;
            float acc = 0.0f;
#pragma unroll
            for (int ni = 0; ni < 8; ni++) {
                int kk = wn * 64 + ni * 8 + tig * 2;
                uchar2 mm = *(const uchar2*)&mask8[mrow + kk];
                float p0 = mm.x ? 0.0f : __expf(c[mi][ni][ro * 2 + 0]);
                float p1 = mm.y ? 0.0f : __expf(c[mi][ni][ro * 2 + 1]);
                *(__half2*)&SM[ql * 136 + kk] = __floats2half2_rn(p0, p1);
                acc += p0 + p1;
            }
            acc += __shfl_xor_sync(0xffffffffu, acc, 1);
            acc += __shfl_xor_sync(0xffffffffu, acc, 2);
            if (tig == 0) atomicAdd(&rowsum[bh * Ll + q], acc);
        }
    __syncthreads();

    // coalesced streaming stores of the P tile
#pragma unroll
    for (int i = 0; i < 8; i++) {
        int u = tid + i * 256;
        int r = u >> 4, s = u & 15;
        int4 val = *(int4*)&SM[r * 136 + s * 8];
        __stcs((int4*)&P[((size_t)bh * Ll + m0 + r) * Ll + n0 + s * 8], val);
    }
}

// ------------------------- pv: attn out + O (cp.async pipelined) ------------
// grid (32 qtile, 32 bh); q-tile 64 rows, BK=64, 32 iterations, double buffer.
__global__ __launch_bounds__(256)
void pv_kernel(const __half* __restrict__ P, const __half* __restrict__ vh,
               const float* __restrict__ invs, float* __restrict__ attn_out,
               __half* __restrict__ xin)
{
    __shared__ __half Ps[2][64 * 72];
    __shared__ __half Vs[2][64 * 72];

    int bh = blockIdx.y;
    int m0 = blockIdx.x * 64;
    const __half* Pg = P + (size_t)bh * Ll * Ll;
    const __half* V  = vh + (size_t)bh * Ll * 64;
    float* aout = attn_out + (size_t)bh * Ll * Ll;

    int tid = threadIdx.x, warp = tid >> 5, lane = tid & 31;
    int wm = warp >> 2, wn = warp & 3;          // 2 x 4 warps, warp tile 32x16
    int grp = lane >> 2, tig = lane & 3;
    int tg = lane >> 3, idx = lane & 7;

    // attn-epilogue mapping: thread owns row er, cols ec..ec+15 of each tile
    int er = tid >> 2;
    int ec = (tid & 3) * 16;
    float invT = invs[bh * Ll + m0 + er];

    float o[2][2][4];
#pragma unroll
    for (int i = 0; i < 2; i++)
#pragma unroll
        for (int j = 0; j < 2; j++)
#pragma unroll
            for (int k = 0; k < 4; k++) o[i][j][k] = 0.0f;

    // issue loads for tile `it` into buffer `buf`
    auto issue = [&](int it, int buf) {
        int k0 = it * 64;
#pragma unroll
        for (int i = 0; i < 2; i++) {
            int u = tid + i * 256; int r = u >> 3, s = u & 7;
            cpa16(&Ps[buf][r * 72 + s * 8], &Pg[((size_t)(m0 + r)) * Ll + k0 + s * 8]);
            cpa16(&Vs[buf][r * 72 + s * 8], &V[(size_t)(k0 + r) * 64 + s * 8]);
        }
        cpa_commit();
    };

    issue(0, 0);

    for (int it = 0; it < 32; it++) {
        int buf = it & 1;
        if (it < 31) { issue(it + 1, buf ^ 1); cpa_wait<1>(); }
        else cpa_wait<0>();
        __syncthreads();

        // decoupled attn store epilogue (coalesced, streaming)
        {
            int k0 = it * 64;
            int4 r0 = *(int4*)&Ps[buf][er * 72 + ec];
            int4 r1 = *(int4*)&Ps[buf][er * 72 + ec + 8];
            __half2* h0 = (__half2*)&r0;
            __half2* h1 = (__half2*)&r1;
            float* dst = &aout[(size_t)(m0 + er) * Ll + k0 + ec];
            float4 f;
#pragma unroll
            for (int j = 0; j < 2; j++) {
                float2 a0 = __half22float2(h0[2 * j + 0]);
                float2 a1 = __half22float2(h0[2 * j + 1]);
                f = make_float4(a0.x * invT, a0.y * invT, a1.x * invT, a1.y * invT);
                __stcs((float4*)(dst + 4 * j), f);
                float2 b0 = __half22float2(h1[2 * j + 0]);
                float2 b1 = __half22float2(h1[2 * j + 1]);
                f = make_float4(b0.x * invT, b0.y * invT, b1.x * invT, b1.y * invT);
                __stcs((float4*)(dst + 8 + 4 * j), f);
            }
        }

        // O += P_unnorm @ V
#pragma unroll
        for (int ks = 0; ks < 4; ks++) {
            uint32_t a[2][4];
#pragma unroll
            for (int mi = 0; mi < 2; mi++) {
                int row = wm * 32 + mi * 16 + (lane & 15);
                int col = ks * 16 + ((lane >> 4) << 3);
                ldm_x4(a[mi], sptr(&Ps[buf][row * 72 + col]));
            }
            uint32_t bb[4];
            {
                int krow = ks * 16 + ((tg & 1) << 3) + idx;
                int col = wn * 16 + ((tg >> 1) << 3);
                ldm_x4_t(bb, sptr(&Vs[buf][krow * 72 + col]));
            }
#pragma unroll
            for (int mi = 0; mi < 2; mi++) {
                mma16816(o[mi][0], a[mi], bb[0], bb[1]);
                mma16816(o[mi][1], a[mi], bb[2], bb[3]);
            }
        }
        __syncthreads();   // protect buf^1 before next issue overwrites it
    }

    // scale O by 1/rowsum, write xin with the reference's permute index
    int hp = bh >> 2, bp = bh & 3;
#pragma unroll
    for (int mi = 0; mi < 2; mi++) {
#pragma unroll
        for (int ro = 0; ro < 2; ro++) {
            int l = m0 + wm * 32 + mi * 16 + ro * 8 + grp;
            float inv = invs[bh * Ll + l];
            size_t n = (size_t)hp * 8192 + (size_t)l * 4 + bp;
#pragma unroll
            for (int ni = 0; ni < 2; ni++) {
                int cC = wn * 16 + ni * 8 + tig * 2;
                *(__half2*)&xin[n * 64 + cC] =
                    __floats2half2_rn(o[mi][ni][ro * 2] * inv, o[mi][ni][ro * 2 + 1] * inv);
            }
        }
    }
}

// ------------------------- layernorm (+ residual) ---------------------------
__global__ __launch_bounds__(128)
void ln_kernel(const float* __restrict__ x2, const float* __restrict__ resid,
               const float* __restrict__ g, const float* __restrict__ bta,
               float* __restrict__ y)
{
    int r = blockIdx.x;
    const float* xr = x2 + (size_t)r * Dd;
    const float* qr = resid + (size_t)r * Dd;
    int t = threadIdx.x;
    float v[4];
    float s = 0.0f, s2 = 0.0f;
#pragma unroll
    for (int i = 0; i < 4; i++) {
        int cI = t + i * 128;
        v[i] = xr[cI] + qr[cI];
        s += v[i]; s2 += v[i] * v[i];
    }
#pragma unroll
    for (int off = 16; off > 0; off >>= 1) {
        s  += __shfl_xor_sync(0xffffffffu, s,  off);
        s2 += __shfl_xor_sync(0xffffffffu, s2, off);
    }
    __shared__ float ss[4], ss2[4];
    int w = t >> 5, lane = t & 31;
    if (lane == 0) { ss[w] = s; ss2[w] = s2; }
    __syncthreads();
    float S = ss[0] + ss[1] + ss[2] + ss[3];
    float S2 = ss2[0] + ss2[1] + ss2[2] + ss2[3];
    float mu = S / Dd;
    float var = S2 / Dd - mu * mu;
    float rstd = rsqrtf(var + LN_EPS);
#pragma unroll
    for (int i = 0; i < 4; i++) {
        int cI = t + i * 128;
        y[(size_t)r * Dd + cI] = (v[i] - mu) * rstd * g[cI] + bta[cI];
    }
}

// ------------------------- host launcher ------------------------------------
extern "C" void kernel_launch(void* const* d_in, const int* in_sizes, int n_in,
                              void* d_out, int out_size)
{
    (void)in_sizes; (void)n_in; (void)out_size;
    const float* q    = (const float*)d_in[0];
    const float* k    = (const float*)d_in[1];
    const float* v    = (const float*)d_in[2];
    const int*   mask = (const int*)d_in[3];
    const float* wq_w = (const float*)d_in[4];
    const float* wq_b = (const float*)d_in[5];
    const float* wv_w = (const float*)d_in[6];
    const float* wv_b = (const float*)d_in[7];
    const float* fc_w = (const float*)d_in[8];
    const float* fc_b = (const float*)d_in[9];
    const float* ln_g = (const float*)d_in[10];
    const float* ln_b = (const float*)d_in[11];

    float* y_out    = (float*)d_out;
    float* attn_out = y_out + (size_t)BL * Dd;

    __half *q16, *k16, *v16, *wq16, *wv16, *wf16, *qh, *kh, *vh, *P, *xin;
    unsigned char* mask8;
    float *rowsum, *x2;
    cudaGetSymbolAddress((void**)&q16,  g_q16);
    cudaGetSymbolAddress((void**)&k16,  g_k16);
    cudaGetSymbolAddress((void**)&v16,  g_v16);
    cudaGetSymbolAddress((void**)&wq16, g_wq16);
    cudaGetSymbolAddress((void**)&wv16, g_wv16);
    cudaGetSymbolAddress((void**)&wf16, g_wf16);
    cudaGetSymbolAddress((void**)&qh,   g_qh);
    cudaGetSymbolAddress((void**)&kh,   g_kh);
    cudaGetSymbolAddress((void**)&vh,   g_vh);
    cudaGetSymbolAddress((void**)&mask8, g_mask8);
    cudaGetSymbolAddress((void**)&P,    g_p);
    cudaGetSymbolAddress((void**)&rowsum, g_rowsum);
    cudaGetSymbolAddress((void**)&xin,  g_xin);
    cudaGetSymbolAddress((void**)&x2,   g_x2);

    const int nBig = BL * Dd;          // 4194304
    const int nW   = Dd * Dd;          // 262144
    const int nM   = Bb * Ll * Ll;     // 16777216
    f2h_kernel<<<nBig / 4 / 256, 256>>>(q, q16, nBig);
    f2h_kernel<<<nBig / 4 / 256, 256>>>(k, k16, nBig);
    f2h_kernel<<<nBig / 4 / 256, 256>>>(v, v16, nBig);
    f2h_kernel<<<nW / 4 / 256, 256>>>(wq_w, wq16, nW);
    f2h_kernel<<<nW / 4 / 256, 256>>>(wv_w, wv16, nW);
    f2h_kernel<<<nW / 4 / 256, 256>>>(fc_w, wf16, nW);
    mask8_kernel<<<nM / 4 / 256, 256>>>(mask, mask8, nM);
    zero_kernel<<<(BH * Ll) / 256, 256>>>(rowsum, BH * Ll);

    dim3 gP(Dd / 128, BL / 128);  // (4, 64)
    gemm_kernel<0><<<gP, 256>>>(q16, wq16, wq_b, qh, Dd, Dd, INV_TEMP);
    gemm_kernel<0><<<gP, 256>>>(k16, wq16, wq_b, kh, Dd, Dd, 1.0f);   // k uses wq (bug preserved)
    gemm_kernel<0><<<gP, 256>>>(v16, wv16, wv_b, vh, Dd, Dd, 1.0f);

    scores_kernel<<<dim3(16, 16, 32), 256>>>(qh, kh, mask8, P, rowsum);
    invert_kernel<<<(BH * Ll) / 256, 256>>>(rowsum, BH * Ll);
    pv_kernel<<<dim3(32, 32), 256>>>(P, vh, rowsum, attn_out, xin);

    gemm_kernel<1><<<gP, 256>>>(xin, wf16, fc_b, x2, Dd, Dd, 1.0f);
    ln_kernel<<<BL, 128>>>(x2, q, ln_g, ln_b, y_out);
}